// round 4
// baseline (speedup 1.0000x reference)
#include <cuda_runtime.h>
#include <math.h>

#define UNITS 1024
#define FEAT  1024
#define GCOLS 4096                 // 4 * UNITS gate columns
#define KSLICES 16
#define KCHUNK (FEAT / KSLICES)    // 64
#define RBLOCKS 8                  // reduce/gate blocks: 8 x 128 = 1024 = UNITS

// Scratch (device globals: no allocation allowed in kernel_launch)
__device__ float g_pxw0[KSLICES][GCOLS];   // partials of x0 @ W
__device__ float g_pxw1[KSLICES][GCOLS];   // partials of x1 @ W
__device__ float g_phu [KSLICES][GCOLS];   // partials of h0 @ U
__device__ float g_z1pre[GCOLS];           // x1@W + b
__device__ float g_h0[UNITS];
__device__ float g_c0[UNITS];
__device__ float g_dot[RBLOCKS][4];        // per-block partial dense dots
__device__ int   g_cnt;                    // last-block arrival counter (zero-init)

__device__ __forceinline__ float sigmoidf_(float x) {
    return 1.0f / (1.0f + expf(-x));
}

// ---------------------------------------------------------------------------
// Kernel 1: partial GEMV  z0_part = x[0,:] @ W,  z1_part = x[1,:] @ W
// grid = (8, KSLICES) = 128 blocks, 128 threads, thread -> 4 consecutive cols,
// KCHUNK=64 rows per slice. W float4 loads fully coalesced.
// ---------------------------------------------------------------------------
__global__ void k_xw(const float* __restrict__ x, const float* __restrict__ W) {
    const int j  = (blockIdx.x * 128 + threadIdx.x) * 4;   // column base
    const int k0 = blockIdx.y * KCHUNK;

    float4 a0 = make_float4(0.f, 0.f, 0.f, 0.f);
    float4 a1 = make_float4(0.f, 0.f, 0.f, 0.f);

    #pragma unroll 16
    for (int kk = 0; kk < KCHUNK; ++kk) {
        const int k = k0 + kk;
        const float4 w = *reinterpret_cast<const float4*>(W + (size_t)k * GCOLS + j);
        const float xa = __ldg(x + k);           // x[0, k]
        const float xb = __ldg(x + FEAT + k);    // x[1, k]
        a0.x += xa * w.x; a0.y += xa * w.y; a0.z += xa * w.z; a0.w += xa * w.w;
        a1.x += xb * w.x; a1.y += xb * w.y; a1.z += xb * w.z; a1.w += xb * w.w;
    }
    *reinterpret_cast<float4*>(&g_pxw0[blockIdx.y][j]) = a0;
    *reinterpret_cast<float4*>(&g_pxw1[blockIdx.y][j]) = a1;
}

// ---------------------------------------------------------------------------
// Kernel 2: reduce x@W partials (+b) and t=0 gate math.
// 8 blocks x 128 threads = 1024 threads; thread owns unit u and loads the 4
// gate stripes at q*1024+u -> every warp load = one full 128B line.
// Writes z1pre (all 4 gate cols), h0, c0. Deterministic fixed-order sums.
// ---------------------------------------------------------------------------
__global__ void k_gate0(const float* __restrict__ b) {
    const int u = blockIdx.x * 128 + threadIdx.x;   // 0..1023

    float s0q[4] = {0.f, 0.f, 0.f, 0.f};
    float s1q[4] = {0.f, 0.f, 0.f, 0.f};
    #pragma unroll 4
    for (int s = 0; s < KSLICES; ++s) {
        #pragma unroll
        for (int q = 0; q < 4; ++q) {
            const int col = (q << 10) + u;
            s0q[q] += g_pxw0[s][col];
            s1q[q] += g_pxw1[s][col];
        }
    }
    float zb[4];
    #pragma unroll
    for (int q = 0; q < 4; ++q) {
        const int col = (q << 10) + u;
        const float bc = __ldg(b + col);
        zb[q] = s0q[q] + bc;
        g_z1pre[col] = s1q[q] + bc;
    }
    // gate order [i, f, g, o]; c_prev = 0 so forget gate irrelevant at t=0
    const float c = sigmoidf_(zb[0]) * zb[2];   // candidate act = identity
    const float h = sigmoidf_(zb[3]) * c;       // output act = identity
    g_c0[u] = c;
    g_h0[u] = h;
}

// ---------------------------------------------------------------------------
// Kernel 3: partial GEMV  z1u_part = h0 @ U  (same structure as k_xw)
// ---------------------------------------------------------------------------
__global__ void k_hu(const float* __restrict__ U) {
    const int j  = (blockIdx.x * 128 + threadIdx.x) * 4;
    const int k0 = blockIdx.y * KCHUNK;

    float4 a = make_float4(0.f, 0.f, 0.f, 0.f);

    #pragma unroll 16
    for (int kk = 0; kk < KCHUNK; ++kk) {
        const int k = k0 + kk;
        const float4 u4 = *reinterpret_cast<const float4*>(U + (size_t)k * GCOLS + j);
        const float h = __ldg(&g_h0[k]);
        a.x += h * u4.x; a.y += h * u4.y; a.z += h * u4.z; a.w += h * u4.w;
    }
    *reinterpret_cast<float4*>(&g_phu[blockIdx.y][j]) = a;
}

// ---------------------------------------------------------------------------
// Kernel 4: reduce h0@U partials + t=1 gates + dense-head dots, then the
// last-arriving block folds the 8 block partials and writes the 4 outputs.
// 8 blocks x 128 threads = 1024 threads = UNITS.
// ---------------------------------------------------------------------------
__global__ void k_final(const float* __restrict__ f,
                        const float* __restrict__ Wd,
                        const float* __restrict__ bd,
                        float* __restrict__ out) {
    __shared__ float red[4][4];
    __shared__ int is_last;
    const int tid = threadIdx.x;
    const int u = blockIdx.x * 128 + tid;           // 0..1023

    float sq[4] = {0.f, 0.f, 0.f, 0.f};
    #pragma unroll 4
    for (int s = 0; s < KSLICES; ++s) {
        #pragma unroll
        for (int q = 0; q < 4; ++q) sq[q] += g_phu[s][(q << 10) + u];
    }
    float z1[4];
    #pragma unroll
    for (int q = 0; q < 4; ++q) z1[q] = sq[q] + g_z1pre[(q << 10) + u];

    const float c1 = sigmoidf_(z1[1]) * g_c0[u] + sigmoidf_(z1[0]) * z1[2];
    const float h1 = sigmoidf_(z1[3]) * c1;
    const float n0 = tanhf(g_h0[u]);
    const float n1 = tanhf(h1);

    const float wd0 = __ldg(Wd + 2 * u);
    const float wd1 = __ldg(Wd + 2 * u + 1);
    float v0 = n0 * wd0;   // -> h_c[0,0]
    float v1 = n0 * wd1;   // -> h_c[0,1]
    float v2 = n1 * wd0;   // -> h_c[1,0]
    float v3 = n1 * wd1;   // -> h_c[1,1]

    const unsigned m = 0xffffffffu;
    const int lane = tid & 31;
    const int wrp  = tid >> 5;
    #pragma unroll
    for (int off = 16; off > 0; off >>= 1) {
        v0 += __shfl_down_sync(m, v0, off);
        v1 += __shfl_down_sync(m, v1, off);
        v2 += __shfl_down_sync(m, v2, off);
        v3 += __shfl_down_sync(m, v3, off);
    }
    if (lane == 0) {
        red[0][wrp] = v0; red[1][wrp] = v1; red[2][wrp] = v2; red[3][wrp] = v3;
    }
    __syncthreads();

    if (tid == 0) {
        float r0 = red[0][0] + red[0][1] + red[0][2] + red[0][3];
        float r1 = red[1][0] + red[1][1] + red[1][2] + red[1][3];
        float r2 = red[2][0] + red[2][1] + red[2][2] + red[2][3];
        float r3 = red[3][0] + red[3][1] + red[3][2] + red[3][3];
        g_dot[blockIdx.x][0] = r0;
        g_dot[blockIdx.x][1] = r1;
        g_dot[blockIdx.x][2] = r2;
        g_dot[blockIdx.x][3] = r3;
        __threadfence();
        const int arrived = atomicAdd(&g_cnt, 1);
        is_last = (arrived == RBLOCKS - 1) ? 1 : 0;
    }
    __syncthreads();

    if (is_last && tid == 0) {
        // fixed fold order -> deterministic
        float r0 = 0.f, r1 = 0.f, r2 = 0.f, r3 = 0.f;
        #pragma unroll
        for (int i = 0; i < RBLOCKS; ++i) {
            r0 += g_dot[i][0];
            r1 += g_dot[i][1];
            r2 += g_dot[i][2];
            r3 += g_dot[i][3];
        }
        const float b0 = __ldg(bd + 0);
        const float b1 = __ldg(bd + 1);
        const float hc00 = tanhf(r0 + b0);   // h_c[0,0]
        const float hc01 = tanhf(r1 + b1);   // h_c[0,1]
        const float hc10 = tanhf(r2 + b0);   // h_c[1,0]
        const float hc11 = tanhf(r3 + b1);   // h_c[1,1]
        const float den  = __ldg(f + 1) - __ldg(f + 2);
        out[0] = hc00;                       // h_out
        out[1] = hc01;
        out[2] = (hc00 - hc10) / den;        // H
        out[3] = (hc01 - hc11) / den;
        g_cnt = 0;                           // reset for next replay
    }
}

// ---------------------------------------------------------------------------
extern "C" void kernel_launch(void* const* d_in, const int* in_sizes, int n_in,
                              void* d_out, int out_size) {
    (void)in_sizes; (void)n_in; (void)out_size;
    const float* x  = (const float*)d_in[0];   // inputs (1, 8192, 1024)
    const float* f  = (const float*)d_in[1];   // f (8192, 1)
    const float* W  = (const float*)d_in[2];   // (1024, 4096)
    const float* U  = (const float*)d_in[3];   // (1024, 4096)
    const float* b  = (const float*)d_in[4];   // (4096,)
    const float* Wd = (const float*)d_in[5];   // (1024, 2)
    const float* bd = (const float*)d_in[6];   // (2,)
    float* out = (float*)d_out;

    dim3 gemv_grid(GCOLS / (128 * 4), KSLICES);   // (8, 16) = 128 blocks
    k_xw   <<<gemv_grid, 128>>>(x, W);
    k_gate0<<<RBLOCKS, 128>>>(b);
    k_hu   <<<gemv_grid, 128>>>(U);
    k_final<<<RBLOCKS, 128>>>(f, Wd, bd, out);
}

// round 5
// speedup vs baseline: 1.3088x; 1.3088x over previous
#include <cuda_runtime.h>
#include <math.h>

#define UNITS 1024
#define FEAT  1024
#define GCOLS 4096                 // 4 * UNITS gate columns
#define CPB   32                   // columns per block
#define NBLK  (GCOLS / CPB)        // 128 blocks
#define RWARP 8                    // k-slicing warps per block (256 threads)
#define KPT   (FEAT / RWARP)       // 128 k-iterations per thread

// Scratch (device globals)
__device__ float g_z0[GCOLS];      // x0@W + b     (complete)
__device__ float g_z1pre[GCOLS];   // x1@W + b     (complete)
__device__ float g_z1[GCOLS];      // x1@W + b + h0@U (complete)

__device__ __forceinline__ float sigmoidf_(float x) {
    return 1.0f / (1.0f + expf(-x));
}

// ---------------------------------------------------------------------------
// Kernel 1: z0 = x[0]@W + b, z1pre = x[1]@W + b — complete per block.
// 128 blocks x 256 threads. Block owns 32 consecutive columns.
// Warp r handles k in [r*128, (r+1)*128); lanes span the 32 columns ->
// every W load is one fully-used 128B line. 8-way fold in shared (fixed order).
// ---------------------------------------------------------------------------
__global__ void k_xw(const float* __restrict__ x, const float* __restrict__ W,
                     const float* __restrict__ b) {
    __shared__ float xs0[FEAT], xs1[FEAT];
    __shared__ float sred[RWARP][2 * CPB];
    const int tid = threadIdx.x;
    const int c   = tid & 31;          // column within block
    const int r   = tid >> 5;          // warp id = k-slice
    const int col = blockIdx.x * CPB + c;

    for (int i = tid; i < FEAT; i += 256) {
        xs0[i] = x[i];
        xs1[i] = x[FEAT + i];
    }
    __syncthreads();

    const float* Wp = W + (size_t)(r * KPT) * GCOLS + col;
    float a0 = 0.f, a1 = 0.f;
    #pragma unroll 8
    for (int kk = 0; kk < KPT; ++kk) {
        const float w = Wp[(size_t)kk * GCOLS];
        const int k = r * KPT + kk;
        a0 = fmaf(xs0[k], w, a0);
        a1 = fmaf(xs1[k], w, a1);
    }
    sred[r][c]       = a0;
    sred[r][CPB + c] = a1;
    __syncthreads();

    if (tid < CPB) {
        float s0 = 0.f, s1 = 0.f;
        #pragma unroll
        for (int rr = 0; rr < RWARP; ++rr) {
            s0 += sred[rr][tid];
            s1 += sred[rr][CPB + tid];
        }
        const int oc = blockIdx.x * CPB + tid;
        const float bc = __ldg(b + oc);
        g_z0[oc]    = s0 + bc;
        g_z1pre[oc] = s1 + bc;
    }
}

// ---------------------------------------------------------------------------
// Kernel 2: z1 = z1pre + h0@U. Each block recomputes h0 from g_z0 (cheap,
// redundant, deterministic), then does the same block-complete GEMV over U.
// ---------------------------------------------------------------------------
__global__ void k_hu(const float* __restrict__ U) {
    __shared__ float h0s[UNITS];
    __shared__ float sred[RWARP][CPB];
    const int tid = threadIdx.x;
    const int c   = tid & 31;
    const int r   = tid >> 5;
    const int col = blockIdx.x * CPB + c;

    // t=0 gate math (c_prev = 0): c0 = sig(zi)*zg, h0 = sig(zo)*c0
    for (int u = tid; u < UNITS; u += 256) {
        const float zi = __ldg(&g_z0[u]);
        const float zg = __ldg(&g_z0[2 * UNITS + u]);
        const float zo = __ldg(&g_z0[3 * UNITS + u]);
        const float c0 = sigmoidf_(zi) * zg;
        h0s[u] = sigmoidf_(zo) * c0;
    }
    __syncthreads();

    const float* Up = U + (size_t)(r * KPT) * GCOLS + col;
    float a = 0.f;
    #pragma unroll 8
    for (int kk = 0; kk < KPT; ++kk) {
        const float w = Up[(size_t)kk * GCOLS];
        a = fmaf(h0s[r * KPT + kk], w, a);
    }
    sred[r][c] = a;
    __syncthreads();

    if (tid < CPB) {
        float s = 0.f;
        #pragma unroll
        for (int rr = 0; rr < RWARP; ++rr) s += sred[rr][tid];
        const int oc = blockIdx.x * CPB + tid;
        g_z1[oc] = s + g_z1pre[oc];
    }
}

// ---------------------------------------------------------------------------
// Kernel 3: one block, 1024 threads = UNITS. Gate math for t=0 (recompute)
// and t=1, dense head (2 outputs x 2 timesteps) via deterministic in-block
// reduction, tanh + finite difference, write 4 outputs.
// ---------------------------------------------------------------------------
__global__ void k_final(const float* __restrict__ f,
                        const float* __restrict__ Wd,
                        const float* __restrict__ bd,
                        float* __restrict__ out) {
    __shared__ float red[4][32];
    const int u = threadIdx.x;   // 0..1023

    const float zi0 = g_z0[u];
    const float zg0 = g_z0[2 * UNITS + u];
    const float zo0 = g_z0[3 * UNITS + u];
    const float c0  = sigmoidf_(zi0) * zg0;
    const float h0  = sigmoidf_(zo0) * c0;

    const float zi1 = g_z1[u];
    const float zf1 = g_z1[UNITS + u];
    const float zg1 = g_z1[2 * UNITS + u];
    const float zo1 = g_z1[3 * UNITS + u];
    const float c1  = sigmoidf_(zf1) * c0 + sigmoidf_(zi1) * zg1;
    const float h1  = sigmoidf_(zo1) * c1;

    const float n0 = tanhf(h0);
    const float n1 = tanhf(h1);

    const float wd0 = __ldg(Wd + 2 * u);
    const float wd1 = __ldg(Wd + 2 * u + 1);
    float v0 = n0 * wd0;   // -> h_c[0,0]
    float v1 = n0 * wd1;   // -> h_c[0,1]
    float v2 = n1 * wd0;   // -> h_c[1,0]
    float v3 = n1 * wd1;   // -> h_c[1,1]

    const unsigned m = 0xffffffffu;
    const int lane = u & 31;
    const int wrp  = u >> 5;
    #pragma unroll
    for (int off = 16; off > 0; off >>= 1) {
        v0 += __shfl_down_sync(m, v0, off);
        v1 += __shfl_down_sync(m, v1, off);
        v2 += __shfl_down_sync(m, v2, off);
        v3 += __shfl_down_sync(m, v3, off);
    }
    if (lane == 0) {
        red[0][wrp] = v0; red[1][wrp] = v1; red[2][wrp] = v2; red[3][wrp] = v3;
    }
    __syncthreads();

    if (wrp == 0) {
        float r0 = red[0][lane];
        float r1 = red[1][lane];
        float r2 = red[2][lane];
        float r3 = red[3][lane];
        #pragma unroll
        for (int off = 16; off > 0; off >>= 1) {
            r0 += __shfl_down_sync(m, r0, off);
            r1 += __shfl_down_sync(m, r1, off);
            r2 += __shfl_down_sync(m, r2, off);
            r3 += __shfl_down_sync(m, r3, off);
        }
        if (lane == 0) {
            const float b0 = __ldg(bd + 0);
            const float b1 = __ldg(bd + 1);
            const float hc00 = tanhf(r0 + b0);   // h_c[0,0]
            const float hc01 = tanhf(r1 + b1);   // h_c[0,1]
            const float hc10 = tanhf(r2 + b0);   // h_c[1,0]
            const float hc11 = tanhf(r3 + b1);   // h_c[1,1]
            const float den  = __ldg(f + 1) - __ldg(f + 2);
            out[0] = hc00;                       // h_out
            out[1] = hc01;
            out[2] = (hc00 - hc10) / den;        // H
            out[3] = (hc01 - hc11) / den;
        }
    }
}

// ---------------------------------------------------------------------------
extern "C" void kernel_launch(void* const* d_in, const int* in_sizes, int n_in,
                              void* d_out, int out_size) {
    (void)in_sizes; (void)n_in; (void)out_size;
    const float* x  = (const float*)d_in[0];   // inputs (1, 8192, 1024)
    const float* f  = (const float*)d_in[1];   // f (8192, 1)
    const float* W  = (const float*)d_in[2];   // (1024, 4096)
    const float* U  = (const float*)d_in[3];   // (1024, 4096)
    const float* b  = (const float*)d_in[4];   // (4096,)
    const float* Wd = (const float*)d_in[5];   // (1024, 2)
    const float* bd = (const float*)d_in[6];   // (2,)
    float* out = (float*)d_out;

    k_xw   <<<NBLK, 256>>>(x, W, b);
    k_hu   <<<NBLK, 256>>>(U);
    k_final<<<1, 1024>>>(f, Wd, bd, out);
}

// round 6
// speedup vs baseline: 1.8846x; 1.4399x over previous
#include <cuda_runtime.h>
#include <math.h>

#define UNITS 1024
#define FEAT  1024
#define GCOLS 4096                 // 4 * UNITS gate columns
#define CPB   32                   // columns per block
#define NBLK  (GCOLS / CPB)        // 128 blocks
#define RWARP 32                   // k-slicing warps per block (1024 threads)
#define KPT   (FEAT / RWARP)       // 32 k-iterations per thread

// Scratch (device globals)
__device__ float g_z0[GCOLS];      // x0@W + b     (complete)
__device__ float g_z1pre[GCOLS];   // x1@W + b     (complete)
__device__ float g_z1[GCOLS];      // x1@W + b + h0@U (complete)

__device__ __forceinline__ float sigmoidf_(float x) {
    return 1.0f / (1.0f + expf(-x));
}

// ---------------------------------------------------------------------------
// Kernel 1: z0 = x[0]@W + b, z1pre = x[1]@W + b — complete per block.
// 128 blocks x 1024 threads (32 warps). Block owns 32 consecutive columns.
// Warp r handles k in [r*32, (r+1)*32); lanes span the 32 columns ->
// every W load is one fully-used 128B line. 32-way fold in shared (fixed order).
// ---------------------------------------------------------------------------
__global__ void __launch_bounds__(1024, 1)
k_xw(const float* __restrict__ x, const float* __restrict__ W,
     const float* __restrict__ b) {
    __shared__ float xs0[FEAT], xs1[FEAT];
    __shared__ float sred[RWARP][2 * CPB];
    const int tid = threadIdx.x;
    const int c   = tid & 31;          // column within block
    const int r   = tid >> 5;          // warp id = k-slice
    const int col = blockIdx.x * CPB + c;

    for (int i = tid; i < FEAT; i += 1024) {
        xs0[i] = x[i];
        xs1[i] = x[FEAT + i];
    }
    __syncthreads();

    const float* Wp = W + (size_t)(r * KPT) * GCOLS + col;
    float a0 = 0.f, a1 = 0.f;
    #pragma unroll
    for (int kk = 0; kk < KPT; ++kk) {
        const float w = Wp[(size_t)kk * GCOLS];
        const int k = r * KPT + kk;
        a0 = fmaf(xs0[k], w, a0);
        a1 = fmaf(xs1[k], w, a1);
    }
    sred[r][c]       = a0;
    sred[r][CPB + c] = a1;
    __syncthreads();

    if (tid < CPB) {
        float s0 = 0.f, s1 = 0.f;
        #pragma unroll
        for (int rr = 0; rr < RWARP; ++rr) {
            s0 += sred[rr][tid];
            s1 += sred[rr][CPB + tid];
        }
        const int oc = blockIdx.x * CPB + tid;
        const float bc = __ldg(b + oc);
        g_z0[oc]    = s0 + bc;
        g_z1pre[oc] = s1 + bc;
    }
}

// ---------------------------------------------------------------------------
// Kernel 2: z1 = z1pre + h0@U. Each block recomputes h0 from g_z0 (cheap,
// redundant, deterministic), then does the same block-complete GEMV over U.
// ---------------------------------------------------------------------------
__global__ void __launch_bounds__(1024, 1)
k_hu(const float* __restrict__ U) {
    __shared__ float h0s[UNITS];
    __shared__ float sred[RWARP][CPB];
    const int tid = threadIdx.x;
    const int c   = tid & 31;
    const int r   = tid >> 5;
    const int col = blockIdx.x * CPB + c;

    // t=0 gate math (c_prev = 0): c0 = sig(zi)*zg, h0 = sig(zo)*c0
    {
        const int u = tid;   // 1024 threads = UNITS
        const float zi = __ldg(&g_z0[u]);
        const float zg = __ldg(&g_z0[2 * UNITS + u]);
        const float zo = __ldg(&g_z0[3 * UNITS + u]);
        const float c0 = sigmoidf_(zi) * zg;
        h0s[u] = sigmoidf_(zo) * c0;
    }
    __syncthreads();

    const float* Up = U + (size_t)(r * KPT) * GCOLS + col;
    float a = 0.f;
    #pragma unroll
    for (int kk = 0; kk < KPT; ++kk) {
        const float w = Up[(size_t)kk * GCOLS];
        a = fmaf(h0s[r * KPT + kk], w, a);
    }
    sred[r][c] = a;
    __syncthreads();

    if (tid < CPB) {
        float s = 0.f;
        #pragma unroll
        for (int rr = 0; rr < RWARP; ++rr) s += sred[rr][tid];
        const int oc = blockIdx.x * CPB + tid;
        g_z1[oc] = s + g_z1pre[oc];
    }
}

// ---------------------------------------------------------------------------
// Kernel 3: one block, 1024 threads = UNITS. Gate math for t=0 (recompute)
// and t=1, dense head (2 outputs x 2 timesteps) via deterministic in-block
// reduction, tanh + finite difference, write 4 outputs.
// ---------------------------------------------------------------------------
__global__ void k_final(const float* __restrict__ f,
                        const float* __restrict__ Wd,
                        const float* __restrict__ bd,
                        float* __restrict__ out) {
    __shared__ float red[4][32];
    const int u = threadIdx.x;   // 0..1023

    const float zi0 = g_z0[u];
    const float zg0 = g_z0[2 * UNITS + u];
    const float zo0 = g_z0[3 * UNITS + u];
    const float c0  = sigmoidf_(zi0) * zg0;
    const float h0  = sigmoidf_(zo0) * c0;

    const float zi1 = g_z1[u];
    const float zf1 = g_z1[UNITS + u];
    const float zg1 = g_z1[2 * UNITS + u];
    const float zo1 = g_z1[3 * UNITS + u];
    const float c1  = sigmoidf_(zf1) * c0 + sigmoidf_(zi1) * zg1;
    const float h1  = sigmoidf_(zo1) * c1;

    const float n0 = tanhf(h0);
    const float n1 = tanhf(h1);

    const float wd0 = __ldg(Wd + 2 * u);
    const float wd1 = __ldg(Wd + 2 * u + 1);
    float v0 = n0 * wd0;   // -> h_c[0,0]
    float v1 = n0 * wd1;   // -> h_c[0,1]
    float v2 = n1 * wd0;   // -> h_c[1,0]
    float v3 = n1 * wd1;   // -> h_c[1,1]

    const unsigned m = 0xffffffffu;
    const int lane = u & 31;
    const int wrp  = u >> 5;
    #pragma unroll
    for (int off = 16; off > 0; off >>= 1) {
        v0 += __shfl_down_sync(m, v0, off);
        v1 += __shfl_down_sync(m, v1, off);
        v2 += __shfl_down_sync(m, v2, off);
        v3 += __shfl_down_sync(m, v3, off);
    }
    if (lane == 0) {
        red[0][wrp] = v0; red[1][wrp] = v1; red[2][wrp] = v2; red[3][wrp] = v3;
    }
    __syncthreads();

    if (wrp == 0) {
        float r0 = red[0][lane];
        float r1 = red[1][lane];
        float r2 = red[2][lane];
        float r3 = red[3][lane];
        #pragma unroll
        for (int off = 16; off > 0; off >>= 1) {
            r0 += __shfl_down_sync(m, r0, off);
            r1 += __shfl_down_sync(m, r1, off);
            r2 += __shfl_down_sync(m, r2, off);
            r3 += __shfl_down_sync(m, r3, off);
        }
        if (lane == 0) {
            const float b0 = __ldg(bd + 0);
            const float b1 = __ldg(bd + 1);
            const float hc00 = tanhf(r0 + b0);   // h_c[0,0]
            const float hc01 = tanhf(r1 + b1);   // h_c[0,1]
            const float hc10 = tanhf(r2 + b0);   // h_c[1,0]
            const float hc11 = tanhf(r3 + b1);   // h_c[1,1]
            const float den  = __ldg(f + 1) - __ldg(f + 2);
            out[0] = hc00;                       // h_out
            out[1] = hc01;
            out[2] = (hc00 - hc10) / den;        // H
            out[3] = (hc01 - hc11) / den;
        }
    }
}

// ---------------------------------------------------------------------------
extern "C" void kernel_launch(void* const* d_in, const int* in_sizes, int n_in,
                              void* d_out, int out_size) {
    (void)in_sizes; (void)n_in; (void)out_size;
    const float* x  = (const float*)d_in[0];   // inputs (1, 8192, 1024)
    const float* f  = (const float*)d_in[1];   // f (8192, 1)
    const float* W  = (const float*)d_in[2];   // (1024, 4096)
    const float* U  = (const float*)d_in[3];   // (1024, 4096)
    const float* b  = (const float*)d_in[4];   // (4096,)
    const float* Wd = (const float*)d_in[5];   // (1024, 2)
    const float* bd = (const float*)d_in[6];   // (2,)
    float* out = (float*)d_out;

    k_xw   <<<NBLK, 1024>>>(x, W, b);
    k_hu   <<<NBLK, 1024>>>(U);
    k_final<<<1, 1024>>>(f, Wd, bd, out);
}

// round 7
// speedup vs baseline: 1.9600x; 1.0400x over previous
#include <cuda_runtime.h>
#include <math.h>

#define UNITS 1024
#define FEAT  1024
#define GCOLS 4096                  // 4 * UNITS gate columns
#define CTILE 128                   // columns per block (32 lanes x float4)
#define NCB   (GCOLS / CTILE)       // 32 column tiles
#define KS    4                     // k-slices across blockIdx.y
#define KROWS (FEAT / KS)           // 256 k-rows per block
#define WARPS 32                    // warps per block (1024 threads)
#define KPW   (KROWS / WARPS)       // 8 k-rows per warp

// Scratch (device globals)
__device__ float4 g_p0[KS][GCOLS / 4];   // partials of x0@W (per k-slice)
__device__ float4 g_p1[KS][GCOLS / 4];   // partials of x1@W
__device__ float4 g_pu[KS][GCOLS / 4];   // partials of h0@U

__device__ __forceinline__ float sigmoidf_(float x) {
    return 1.0f / (1.0f + expf(-x));
}

// ---------------------------------------------------------------------------
// Kernel 1: partial GEMV over W for timesteps 0 and 1.
// grid = (NCB, KS) = (32, 4) = 128 blocks x 1024 threads.
// Block (cb, ks): columns [cb*128, cb*128+128), k in [ks*256, ks*256+256).
// Lane loads float4 of 4 consecutive columns -> 512B per warp load.
// Warp r covers k-rows r*8..r*8+7. 32-way fixed-order fold in shared.
// ---------------------------------------------------------------------------
__global__ void __launch_bounds__(1024, 1)
k_xw(const float* __restrict__ x, const float* __restrict__ W) {
    __shared__ float  xs0[KROWS], xs1[KROWS];
    __shared__ float4 sred0[WARPS][32];
    __shared__ float4 sred1[WARPS][32];
    const int tid  = threadIdx.x;
    const int lane = tid & 31;
    const int r    = tid >> 5;
    const int cb   = blockIdx.x;
    const int ks   = blockIdx.y;
    const int colv = cb * 32 + lane;          // float4-column index (0..1023)
    const int kbase = ks * KROWS;

    for (int i = tid; i < KROWS; i += 1024) {
        xs0[i] = x[kbase + i];
        xs1[i] = x[FEAT + kbase + i];
    }
    __syncthreads();

    const float4* Wp = reinterpret_cast<const float4*>(W)
                     + (size_t)(kbase + r * KPW) * (GCOLS / 4) + colv;
    float4 a0 = make_float4(0.f, 0.f, 0.f, 0.f);
    float4 a1 = make_float4(0.f, 0.f, 0.f, 0.f);
    #pragma unroll
    for (int kk = 0; kk < KPW; ++kk) {
        const float4 w = Wp[(size_t)kk * (GCOLS / 4)];
        const float xa = xs0[r * KPW + kk];
        const float xb = xs1[r * KPW + kk];
        a0.x = fmaf(xa, w.x, a0.x); a0.y = fmaf(xa, w.y, a0.y);
        a0.z = fmaf(xa, w.z, a0.z); a0.w = fmaf(xa, w.w, a0.w);
        a1.x = fmaf(xb, w.x, a1.x); a1.y = fmaf(xb, w.y, a1.y);
        a1.z = fmaf(xb, w.z, a1.z); a1.w = fmaf(xb, w.w, a1.w);
    }
    sred0[r][lane] = a0;
    sred1[r][lane] = a1;
    __syncthreads();

    if (tid < 32) {
        float4 s0 = make_float4(0.f, 0.f, 0.f, 0.f);
        #pragma unroll
        for (int rr = 0; rr < WARPS; ++rr) {
            const float4 v = sred0[rr][tid];
            s0.x += v.x; s0.y += v.y; s0.z += v.z; s0.w += v.w;
        }
        g_p0[ks][cb * 32 + tid] = s0;
    } else if (tid < 64) {
        const int c = tid - 32;
        float4 s1 = make_float4(0.f, 0.f, 0.f, 0.f);
        #pragma unroll
        for (int rr = 0; rr < WARPS; ++rr) {
            const float4 v = sred1[rr][c];
            s1.x += v.x; s1.y += v.y; s1.z += v.z; s1.w += v.w;
        }
        g_p1[ks][cb * 32 + c] = s1;
    }
}

// ---------------------------------------------------------------------------
// Helper: fold the KS partials of a gate column (fixed order) — scalar view.
// ---------------------------------------------------------------------------
__device__ __forceinline__ float fold_p(const float4 (*p)[GCOLS / 4], int col) {
    const float* base = reinterpret_cast<const float*>(p);
    float s = 0.f;
    #pragma unroll
    for (int sI = 0; sI < KS; ++sI) s += base[sI * GCOLS + col];
    return s;
}

// ---------------------------------------------------------------------------
// Kernel 2: partial GEMV over U. Same geometry as k_xw. Each block first
// reconstructs the 256 h0 values it needs from the x@W partials (+b):
// c0 = sig(zi)*zg, h0 = sig(zo)*c0  (c_prev = 0).
// ---------------------------------------------------------------------------
__global__ void __launch_bounds__(1024, 1)
k_hu(const float* __restrict__ U, const float* __restrict__ b) {
    __shared__ float  h0s[KROWS];
    __shared__ float4 sred[WARPS][32];
    const int tid  = threadIdx.x;
    const int lane = tid & 31;
    const int r    = tid >> 5;
    const int cb   = blockIdx.x;
    const int ks   = blockIdx.y;
    const int colv = cb * 32 + lane;
    const int kbase = ks * KROWS;

    if (tid < KROWS) {
        const int u = kbase + tid;
        const float zi = fold_p(g_p0, u)             + __ldg(b + u);
        const float zg = fold_p(g_p0, 2 * UNITS + u) + __ldg(b + 2 * UNITS + u);
        const float zo = fold_p(g_p0, 3 * UNITS + u) + __ldg(b + 3 * UNITS + u);
        const float c0 = sigmoidf_(zi) * zg;
        h0s[tid] = sigmoidf_(zo) * c0;
    }
    __syncthreads();

    const float4* Up = reinterpret_cast<const float4*>(U)
                     + (size_t)(kbase + r * KPW) * (GCOLS / 4) + colv;
    float4 a = make_float4(0.f, 0.f, 0.f, 0.f);
    #pragma unroll
    for (int kk = 0; kk < KPW; ++kk) {
        const float4 w = Up[(size_t)kk * (GCOLS / 4)];
        const float h = h0s[r * KPW + kk];
        a.x = fmaf(h, w.x, a.x); a.y = fmaf(h, w.y, a.y);
        a.z = fmaf(h, w.z, a.z); a.w = fmaf(h, w.w, a.w);
    }
    sred[r][lane] = a;
    __syncthreads();

    if (tid < 32) {
        float4 s = make_float4(0.f, 0.f, 0.f, 0.f);
        #pragma unroll
        for (int rr = 0; rr < WARPS; ++rr) {
            const float4 v = sred[rr][tid];
            s.x += v.x; s.y += v.y; s.z += v.z; s.w += v.w;
        }
        g_pu[ks][cb * 32 + tid] = s;
    }
}

// ---------------------------------------------------------------------------
// Kernel 3: one block, 1024 threads = UNITS. Fold all partials, gate math for
// t=0 and t=1, dense head via deterministic in-block reduction, finite diff.
// ---------------------------------------------------------------------------
__global__ void k_final(const float* __restrict__ f,
                        const float* __restrict__ b,
                        const float* __restrict__ Wd,
                        const float* __restrict__ bd,
                        float* __restrict__ out) {
    __shared__ float red[4][32];
    const int u = threadIdx.x;   // 0..1023

    // t=0 gates
    const float zi0 = fold_p(g_p0, u)             + __ldg(b + u);
    const float zg0 = fold_p(g_p0, 2 * UNITS + u) + __ldg(b + 2 * UNITS + u);
    const float zo0 = fold_p(g_p0, 3 * UNITS + u) + __ldg(b + 3 * UNITS + u);
    const float c0  = sigmoidf_(zi0) * zg0;
    const float h0  = sigmoidf_(zo0) * c0;

    // t=1 gates: z1 = x1@W + b + h0@U
    const float zi1 = fold_p(g_p1, u)             + fold_p(g_pu, u)             + __ldg(b + u);
    const float zf1 = fold_p(g_p1, UNITS + u)     + fold_p(g_pu, UNITS + u)     + __ldg(b + UNITS + u);
    const float zg1 = fold_p(g_p1, 2 * UNITS + u) + fold_p(g_pu, 2 * UNITS + u) + __ldg(b + 2 * UNITS + u);
    const float zo1 = fold_p(g_p1, 3 * UNITS + u) + fold_p(g_pu, 3 * UNITS + u) + __ldg(b + 3 * UNITS + u);
    const float c1  = sigmoidf_(zf1) * c0 + sigmoidf_(zi1) * zg1;
    const float h1  = sigmoidf_(zo1) * c1;

    const float n0 = tanhf(h0);
    const float n1 = tanhf(h1);

    const float wd0 = __ldg(Wd + 2 * u);
    const float wd1 = __ldg(Wd + 2 * u + 1);
    float v0 = n0 * wd0;   // -> h_c[0,0]
    float v1 = n0 * wd1;   // -> h_c[0,1]
    float v2 = n1 * wd0;   // -> h_c[1,0]
    float v3 = n1 * wd1;   // -> h_c[1,1]

    const unsigned m = 0xffffffffu;
    const int lane = u & 31;
    const int wrp  = u >> 5;
    #pragma unroll
    for (int off = 16; off > 0; off >>= 1) {
        v0 += __shfl_down_sync(m, v0, off);
        v1 += __shfl_down_sync(m, v1, off);
        v2 += __shfl_down_sync(m, v2, off);
        v3 += __shfl_down_sync(m, v3, off);
    }
    if (lane == 0) {
        red[0][wrp] = v0; red[1][wrp] = v1; red[2][wrp] = v2; red[3][wrp] = v3;
    }
    __syncthreads();

    if (wrp == 0) {
        float r0 = red[0][lane];
        float r1 = red[1][lane];
        float r2 = red[2][lane];
        float r3 = red[3][lane];
        #pragma unroll
        for (int off = 16; off > 0; off >>= 1) {
            r0 += __shfl_down_sync(m, r0, off);
            r1 += __shfl_down_sync(m, r1, off);
            r2 += __shfl_down_sync(m, r2, off);
            r3 += __shfl_down_sync(m, r3, off);
        }
        if (lane == 0) {
            const float b0 = __ldg(bd + 0);
            const float b1 = __ldg(bd + 1);
            const float hc00 = tanhf(r0 + b0);   // h_c[0,0]
            const float hc01 = tanhf(r1 + b1);   // h_c[0,1]
            const float hc10 = tanhf(r2 + b0);   // h_c[1,0]
            const float hc11 = tanhf(r3 + b1);   // h_c[1,1]
            const float den  = __ldg(f + 1) - __ldg(f + 2);
            out[0] = hc00;                       // h_out
            out[1] = hc01;
            out[2] = (hc00 - hc10) / den;        // H
            out[3] = (hc01 - hc11) / den;
        }
    }
}

// ---------------------------------------------------------------------------
extern "C" void kernel_launch(void* const* d_in, const int* in_sizes, int n_in,
                              void* d_out, int out_size) {
    (void)in_sizes; (void)n_in; (void)out_size;
    const float* x  = (const float*)d_in[0];   // inputs (1, 8192, 1024)
    const float* f  = (const float*)d_in[1];   // f (8192, 1)
    const float* W  = (const float*)d_in[2];   // (1024, 4096)
    const float* U  = (const float*)d_in[3];   // (1024, 4096)
    const float* b  = (const float*)d_in[4];   // (4096,)
    const float* Wd = (const float*)d_in[5];   // (1024, 2)
    const float* bd = (const float*)d_in[6];   // (2,)
    float* out = (float*)d_out;

    dim3 grid(NCB, KS);   // (32, 4) = 128 blocks
    k_xw   <<<grid, 1024>>>(x, W);
    k_hu   <<<grid, 1024>>>(U, b);
    k_final<<<1, 1024>>>(f, b, Wd, bd, out);
}